// round 10
// baseline (speedup 1.0000x reference)
#include <cuda_runtime.h>
#include <cuda_bf16.h>
#include <cstdint>

#define G  32
#define NV 64
#define H  256
#define M_ROWS (G * NV)

// Scratch (allocation-free rule: __device__ globals)
__device__ float g_C[M_ROWS * H];
__device__ float g_Y[M_ROWS * H];

// ---------------------------------------------------------------------------
// Stage A: TF32 tensor-core GEMM, no explicit CVT (HMMA.tf32 reads top 19 bits).
//   out[m][n] = sum_h z[m][h] * W[n][h] + b[n]
// Block tile 64(M) x 64(N), KC=32 double-buffered cp.async, 8 warps,
// warp tile 16(M) x 32(N). Grid (H/64, M/64, 2) = 256 blocks.
// ---------------------------------------------------------------------------
#define KC   32
#define LDK  36
#define NCH  (H / KC)   // 8 chunks

__device__ __forceinline__ void cpa16(uint32_t dst, const float* src) {
    asm volatile("cp.async.cg.shared.global [%0], [%1], 16;" :: "r"(dst), "l"(src));
}

__device__ __forceinline__ void mma_tf32(float c[4], const uint32_t a[4], const uint32_t b[2]) {
    asm volatile(
        "mma.sync.aligned.m16n8k8.row.col.f32.tf32.tf32.f32 "
        "{%0,%1,%2,%3}, {%4,%5,%6,%7}, {%8,%9}, {%0,%1,%2,%3};"
        : "+f"(c[0]), "+f"(c[1]), "+f"(c[2]), "+f"(c[3])
        : "r"(a[0]), "r"(a[1]), "r"(a[2]), "r"(a[3]), "r"(b[0]), "r"(b[1]));
}

__global__ void __launch_bounds__(256, 2) gemm_tc_kernel(
    const float* __restrict__ z,
    const float* __restrict__ Wc, const float* __restrict__ bc,
    const float* __restrict__ Wy, const float* __restrict__ by)
{
    const float* __restrict__ W    = blockIdx.z ? Wy : Wc;
    const float* __restrict__ bias = blockIdx.z ? by : bc;
    float* __restrict__ outp       = blockIdx.z ? g_Y : g_C;

    __shared__ float As[2][64 * LDK];
    __shared__ float Bs[2][64 * LDK];

    const int t    = threadIdx.x;
    const int warp = t >> 5;
    const int lane = t & 31;
    const int g    = lane >> 2;
    const int tg   = lane & 3;
    const int wm   = warp & 3;
    const int wn   = warp >> 2;
    const int m0   = blockIdx.y * 64;
    const int n0   = blockIdx.x * 64;

    const int r0s = t >> 3,         kg0 = t & 7;
    const int r1s = (t + 256) >> 3, kg1 = (t + 256) & 7;

    float acc[4][4];
#pragma unroll
    for (int nt = 0; nt < 4; nt++)
#pragma unroll
        for (int i = 0; i < 4; i++) acc[nt][i] = 0.0f;

    auto issue = [&](int c) {
        const int buf = c & 1;
        const int kc0 = c * KC;
        uint32_t asb = (uint32_t)__cvta_generic_to_shared(&As[buf][0]);
        uint32_t bsb = (uint32_t)__cvta_generic_to_shared(&Bs[buf][0]);
        cpa16(asb + (uint32_t)(r0s * LDK + kg0 * 4) * 4, z + (size_t)(m0 + r0s) * H + kc0 + kg0 * 4);
        cpa16(asb + (uint32_t)(r1s * LDK + kg1 * 4) * 4, z + (size_t)(m0 + r1s) * H + kc0 + kg1 * 4);
        cpa16(bsb + (uint32_t)(r0s * LDK + kg0 * 4) * 4, W + (size_t)(n0 + r0s) * H + kc0 + kg0 * 4);
        cpa16(bsb + (uint32_t)(r1s * LDK + kg1 * 4) * 4, W + (size_t)(n0 + r1s) * H + kc0 + kg1 * 4);
        asm volatile("cp.async.commit_group;");
    };

    issue(0);

    for (int c = 0; c < NCH; c++) {
        if (c + 1 < NCH) {
            issue(c + 1);
            asm volatile("cp.async.wait_group 1;");
        } else {
            asm volatile("cp.async.wait_group 0;");
        }
        __syncthreads();

        const uint32_t* as = reinterpret_cast<const uint32_t*>(&As[c & 1][0]);
        const uint32_t* bs = reinterpret_cast<const uint32_t*>(&Bs[c & 1][0]);

#pragma unroll
        for (int ks = 0; ks < KC / 8; ks++) {
            const int kk = ks * 8;
            uint32_t afr[4];
            {
                const uint32_t* ap = as + (wm * 16 + g) * LDK + kk + tg;
                afr[0] = ap[0];
                afr[1] = ap[8 * LDK];
                afr[2] = ap[4];
                afr[3] = ap[8 * LDK + 4];
            }
            uint32_t bfr[4][2];
#pragma unroll
            for (int nt = 0; nt < 4; nt++) {
                const uint32_t* bp = bs + (wn * 32 + nt * 8 + g) * LDK + kk + tg;
                bfr[nt][0] = bp[0];
                bfr[nt][1] = bp[4];
            }
#pragma unroll
            for (int nt = 0; nt < 4; nt++)
                mma_tf32(acc[nt], afr, bfr[nt]);
        }
        __syncthreads();
    }

#pragma unroll
    for (int nt = 0; nt < 4; nt++) {
        const int col = n0 + wn * 32 + nt * 8 + 2 * tg;
        const float b0 = __ldg(&bias[col]);
        const float b1 = __ldg(&bias[col + 1]);
        const int row = m0 + wm * 16 + g;
        float2 o0 = {acc[nt][0] + b0, acc[nt][1] + b1};
        float2 o1 = {acc[nt][2] + b0, acc[nt][3] + b1};
        *reinterpret_cast<float2*>(&outp[(size_t)row * H + col])       = o0;
        *reinterpret_cast<float2*>(&outp[(size_t)(row + 8) * H + col]) = o1;
    }
}

// ---------------------------------------------------------------------------
// Stage B: pairwise sigmoid sum.
// Block = 64 threads, owns (2 output rows) x (half of H: 128 h = 64 float2).
// Grid (NV/2, G, 2). One compacted cp.async fill of Y rows into smem
// (nact x 128 floats <= 32 KB), ONE barrier, then a pure linear
// LDS.64 -> FFMA(imm 0.5) -> MUFU.TANH -> FADD loop.
// sigmoid(x)=0.5*tanh(0.5*x)+0.5 folded.
// OUTPUT ROW STRIDE = H/2 float2 (R8/R9 bug: used HB2=64, scrambling rows).
// ---------------------------------------------------------------------------
#define RPB 2
#define HB  128          // h columns per block
#define HB2 (HB / 2)     // float2 per row in SMEM tile = 64
#define OST (H / 2)      // output row stride in float2 = 128

__device__ __forceinline__ float tanhx(float x) {
    float th;
    asm("tanh.approx.f32 %0, %1;" : "=f"(th) : "f"(x));
    return th;
}

__global__ void __launch_bounds__(64) attn_kernel(
    const float* __restrict__ mask, float* __restrict__ out)
{
    extern __shared__ float ysh[];       // [nact rows][128 floats] compacted
    __shared__ int acts[NV];
    __shared__ int s_cnt[2];
    __shared__ int s_nact;

    const int gg = blockIdx.y;
    const int r0 = blockIdx.x * RPB;
    const int hb = blockIdx.z;           // h half
    const int t  = threadIdx.x;          // 0..63, float2 col = hb*64 + t

    // ---- in-block compaction (all 64 threads) ----
    {
        const bool act = (mask[gg * NV + t] > 0.5f);
        const unsigned bal = __ballot_sync(0xffffffffu, act);
        if ((t & 31) == 0) s_cnt[t >> 5] = __popc(bal);
        __syncthreads();
        const int warp = t >> 5, lane = t & 31;
        const int a0 = s_cnt[0], a1 = s_cnt[1];
        const int nact = a0 + a1;
        const int pre  = __popc(bal & ((1u << lane) - 1u));
        const int preI = lane - pre;
        const int pos = act ? ((warp ? a0 : 0) + pre)
                            : (nact + (warp ? (32 - a0) : 0) + preI);
        acts[pos] = t;
        if (t == 0) s_nact = nact;
        __syncthreads();
    }

    const int nact = s_nact;
    const float* __restrict__ cg =
        g_C + (size_t)gg * NV * H + hb * HB + 2 * t;
    float2* __restrict__ outg =
        reinterpret_cast<float2*>(out + (size_t)gg * NV * H + hb * HB) + t;

    if (r0 >= nact) {                    // fully inactive block: zero-fill, done
        float2 zz = {0.0f, 0.0f};
#pragma unroll
        for (int r = 0; r < RPB; r++)
            outg[acts[r0 + r] * OST] = zz;
        return;
    }

    // ---- one-shot compacted fill: smem row k = Y[acts[k]][hb*128 .. +128) ----
    {
        const float* __restrict__ ygb = g_Y + (size_t)gg * NV * H + hb * HB;
        const uint32_t sb = (uint32_t)__cvta_generic_to_shared(&ysh[0]);
        const int nch = nact * (HB / 4);          // 16B chunks (32 per row)
        for (int s = t; s < nch; s += 64) {
            const int row = s >> 5;
            const int q   = s & 31;
            cpa16(sb + (uint32_t)(row * HB + q * 4) * 4,
                  ygb + (size_t)acts[row] * H + q * 4);
        }
        asm volatile("cp.async.commit_group;");
        asm volatile("cp.async.wait_group 0;");
        __syncthreads();
    }

    float2 a2[RPB], acc[RPB];
#pragma unroll
    for (int r = 0; r < RPB; r++) {
        float2 c = *reinterpret_cast<const float2*>(cg + (size_t)acts[r0 + r] * H);
        a2[r].x = 0.5f * c.x;
        a2[r].y = 0.5f * c.y;
        acc[r].x = 0.0f;
        acc[r].y = 0.0f;
    }

    const float2* __restrict__ ys2 = reinterpret_cast<const float2*>(ysh);

    int jj = 0;
    for (; jj + 4 <= nact; jj += 4) {
        float2 yv[4];
#pragma unroll
        for (int u = 0; u < 4; u++) yv[u] = ys2[(jj + u) * HB2 + t];
#pragma unroll
        for (int u = 0; u < 4; u++) {
#pragma unroll
            for (int r = 0; r < RPB; r++) {
                acc[r].x += tanhx(fmaf(0.5f, yv[u].x, a2[r].x));
                acc[r].y += tanhx(fmaf(0.5f, yv[u].y, a2[r].y));
            }
        }
    }
    for (; jj < nact; jj++) {
        const float2 y = ys2[jj * HB2 + t];
#pragma unroll
        for (int r = 0; r < RPB; r++) {
            acc[r].x += tanhx(fmaf(0.5f, y.x, a2[r].x));
            acc[r].y += tanhx(fmaf(0.5f, y.y, a2[r].y));
        }
    }

    const float inv    = 1.0f / (float)nact;
    const float half_n = 0.5f * (float)nact;
#pragma unroll
    for (int r = 0; r < RPB; r++) {
        const int rr = r0 + r;
        float2 v;
        if (rr < nact) {                 // straddling block's tail row -> 0
            v.x = (0.5f * acc[r].x + half_n) * inv;
            v.y = (0.5f * acc[r].y + half_n) * inv;
        } else {
            v.x = 0.0f;
            v.y = 0.0f;
        }
        outg[acts[rr] * OST] = v;
    }
}

// ---------------------------------------------------------------------------
// kernel_launch
// ---------------------------------------------------------------------------
extern "C" void kernel_launch(void* const* d_in, const int* in_sizes, int n_in,
                              void* d_out, int out_size)
{
    const float *z = nullptr, *mask = nullptr;
    const float *Wc = nullptr, *bc = nullptr, *Wy = nullptr, *by = nullptr;

    for (int i = 0; i < n_in; i++) {
        int s = in_sizes[i];
        const float* p = (const float*)d_in[i];
        if (s == M_ROWS * H)       z = p;
        else if (s == M_ROWS)      mask = p;
        else if (s == H * H)       { if (!Wc) Wc = p; else Wy = p; }
        else if (s == H)           { if (!bc) bc = p; else by = p; }
    }

    float* out = (float*)d_out;

    gemm_tc_kernel<<<dim3(H / 64, M_ROWS / 64, 2), 256>>>(z, Wc, bc, Wy, by);

    const size_t ysmem = (size_t)NV * HB * sizeof(float);   // 32 KB worst case
    attn_kernel<<<dim3(NV / RPB, G, 2), 64, ysmem>>>(mask, out);
}

// round 11
// speedup vs baseline: 1.0467x; 1.0467x over previous
#include <cuda_runtime.h>
#include <cuda_bf16.h>
#include <cstdint>

#define G  32
#define NV 64
#define H  256
#define M_ROWS (G * NV)

// Scratch (allocation-free rule: __device__ globals)
__device__ float g_C[M_ROWS * H];
__device__ float g_Y[M_ROWS * H];

// ---------------------------------------------------------------------------
// Stage A: TF32 tensor-core GEMM, no explicit CVT (HMMA.tf32 reads top 19 bits).
//   out[m][n] = sum_h z[m][h] * W[n][h] + b[n]
// Block tile 64(M) x 64(N), KC=32 double-buffered cp.async, 8 warps,
// warp tile 16(M) x 32(N). Grid (H/64, M/64, 2) = 256 blocks.
// ---------------------------------------------------------------------------
#define KC   32
#define LDK  36
#define NCH  (H / KC)   // 8 chunks

__device__ __forceinline__ void cpa16(uint32_t dst, const float* src) {
    asm volatile("cp.async.cg.shared.global [%0], [%1], 16;" :: "r"(dst), "l"(src));
}

__device__ __forceinline__ void mma_tf32(float c[4], const uint32_t a[4], const uint32_t b[2]) {
    asm volatile(
        "mma.sync.aligned.m16n8k8.row.col.f32.tf32.tf32.f32 "
        "{%0,%1,%2,%3}, {%4,%5,%6,%7}, {%8,%9}, {%0,%1,%2,%3};"
        : "+f"(c[0]), "+f"(c[1]), "+f"(c[2]), "+f"(c[3])
        : "r"(a[0]), "r"(a[1]), "r"(a[2]), "r"(a[3]), "r"(b[0]), "r"(b[1]));
}

__global__ void __launch_bounds__(256, 2) gemm_tc_kernel(
    const float* __restrict__ z,
    const float* __restrict__ Wc, const float* __restrict__ bc,
    const float* __restrict__ Wy, const float* __restrict__ by)
{
    const float* __restrict__ W    = blockIdx.z ? Wy : Wc;
    const float* __restrict__ bias = blockIdx.z ? by : bc;
    float* __restrict__ outp       = blockIdx.z ? g_Y : g_C;

    __shared__ float As[2][64 * LDK];
    __shared__ float Bs[2][64 * LDK];

    const int t    = threadIdx.x;
    const int warp = t >> 5;
    const int lane = t & 31;
    const int g    = lane >> 2;
    const int tg   = lane & 3;
    const int wm   = warp & 3;
    const int wn   = warp >> 2;
    const int m0   = blockIdx.y * 64;
    const int n0   = blockIdx.x * 64;

    const int r0s = t >> 3,         kg0 = t & 7;
    const int r1s = (t + 256) >> 3, kg1 = (t + 256) & 7;

    float acc[4][4];
#pragma unroll
    for (int nt = 0; nt < 4; nt++)
#pragma unroll
        for (int i = 0; i < 4; i++) acc[nt][i] = 0.0f;

    auto issue = [&](int c) {
        const int buf = c & 1;
        const int kc0 = c * KC;
        uint32_t asb = (uint32_t)__cvta_generic_to_shared(&As[buf][0]);
        uint32_t bsb = (uint32_t)__cvta_generic_to_shared(&Bs[buf][0]);
        cpa16(asb + (uint32_t)(r0s * LDK + kg0 * 4) * 4, z + (size_t)(m0 + r0s) * H + kc0 + kg0 * 4);
        cpa16(asb + (uint32_t)(r1s * LDK + kg1 * 4) * 4, z + (size_t)(m0 + r1s) * H + kc0 + kg1 * 4);
        cpa16(bsb + (uint32_t)(r0s * LDK + kg0 * 4) * 4, W + (size_t)(n0 + r0s) * H + kc0 + kg0 * 4);
        cpa16(bsb + (uint32_t)(r1s * LDK + kg1 * 4) * 4, W + (size_t)(n0 + r1s) * H + kc0 + kg1 * 4);
        asm volatile("cp.async.commit_group;");
    };

    issue(0);

    for (int c = 0; c < NCH; c++) {
        if (c + 1 < NCH) {
            issue(c + 1);
            asm volatile("cp.async.wait_group 1;");
        } else {
            asm volatile("cp.async.wait_group 0;");
        }
        __syncthreads();

        const uint32_t* as = reinterpret_cast<const uint32_t*>(&As[c & 1][0]);
        const uint32_t* bs = reinterpret_cast<const uint32_t*>(&Bs[c & 1][0]);

#pragma unroll
        for (int ks = 0; ks < KC / 8; ks++) {
            const int kk = ks * 8;
            uint32_t afr[4];
            {
                const uint32_t* ap = as + (wm * 16 + g) * LDK + kk + tg;
                afr[0] = ap[0];
                afr[1] = ap[8 * LDK];
                afr[2] = ap[4];
                afr[3] = ap[8 * LDK + 4];
            }
            uint32_t bfr[4][2];
#pragma unroll
            for (int nt = 0; nt < 4; nt++) {
                const uint32_t* bp = bs + (wn * 32 + nt * 8 + g) * LDK + kk + tg;
                bfr[nt][0] = bp[0];
                bfr[nt][1] = bp[4];
            }
#pragma unroll
            for (int nt = 0; nt < 4; nt++)
                mma_tf32(acc[nt], afr, bfr[nt]);
        }
        __syncthreads();
    }

#pragma unroll
    for (int nt = 0; nt < 4; nt++) {
        const int col = n0 + wn * 32 + nt * 8 + 2 * tg;
        const float b0 = __ldg(&bias[col]);
        const float b1 = __ldg(&bias[col + 1]);
        const int row = m0 + wm * 16 + g;
        float2 o0 = {acc[nt][0] + b0, acc[nt][1] + b1};
        float2 o1 = {acc[nt][2] + b0, acc[nt][3] + b1};
        *reinterpret_cast<float2*>(&outp[(size_t)row * H + col])       = o0;
        *reinterpret_cast<float2*>(&outp[(size_t)(row + 8) * H + col]) = o1;
    }
}

// ---------------------------------------------------------------------------
// Stage B: pairwise sigmoid sum, occupancy-first layout.
// Block = 128 threads = 32 float2-cols x 4 rows (row owned by warp).
// Each block covers a QUARTER of H (HB=64 floats) -> dynamic smem 16 KB
// -> ~13 blocks/SM (~52 warps). Grid (NV/4, G, 4) = 2048 blocks ~= 1 wave.
// One compacted cp.async fill (smem row k = Y[acts[k]][quarter]), one
// barrier, then linear LDS.64 -> FFMA(imm 0.5) -> MUFU.TANH -> FADD,
// j unrolled x8 (16 independent chains / thread).
// sigmoid(x)=0.5*tanh(0.5*x)+0.5 folded. Output row stride H (floats).
// ---------------------------------------------------------------------------
#define RPB  4
#define HB   64          // h floats per block
#define HB2  (HB / 2)    // float2 cols per block = 32

__device__ __forceinline__ float tanhx(float x) {
    float th;
    asm("tanh.approx.f32 %0, %1;" : "=f"(th) : "f"(x));
    return th;
}

__global__ void __launch_bounds__(128) attn_kernel(
    const float* __restrict__ mask, float* __restrict__ out)
{
    extern __shared__ float ysh[];       // [NV rows][64 floats] compacted
    __shared__ int acts[NV];
    __shared__ int s_cnt[2];
    __shared__ int s_nact;

    const int gg  = blockIdx.y;
    const int r0  = blockIdx.x * RPB;
    const int hb  = blockIdx.z;          // h quarter
    const int t   = threadIdx.x;
    const int col = t & 31;              // float2 col within quarter
    const int r   = t >> 5;              // 0..3 row slot (== warp id)

    // ---- in-block compaction (threads 0..63; syncs unguarded) ----
    bool act = false;
    unsigned bal = 0;
    if (t < NV) {
        act = (mask[gg * NV + t] > 0.5f);
        bal = __ballot_sync(0xffffffffu, act);
        if ((t & 31) == 0) s_cnt[t >> 5] = __popc(bal);
    }
    __syncthreads();
    if (t < NV) {
        const int warp = t >> 5, lane = t & 31;
        const int a0 = s_cnt[0], a1 = s_cnt[1];
        const int nact = a0 + a1;
        const int pre  = __popc(bal & ((1u << lane) - 1u));
        const int preI = lane - pre;
        const int pos = act ? ((warp ? a0 : 0) + pre)
                            : (nact + (warp ? (32 - a0) : 0) + preI);
        acts[pos] = t;
        if (t == 0) s_nact = nact;
    }
    __syncthreads();

    const int nact = s_nact;
    const int rr   = r0 + r;
    const int row_i = acts[rr];          // rr <= 63 always

    float2* __restrict__ outp = reinterpret_cast<float2*>(
        out + (size_t)gg * NV * H + (size_t)row_i * H + hb * HB) + col;

    if (r0 >= nact) {                    // fully inactive block
        outp[0] = make_float2(0.0f, 0.0f);
        return;
    }

    // ---- one-shot compacted fill: smem row k = Y[acts[k]][hb*64 .. +64) ----
    {
        const float* __restrict__ ygb = g_Y + (size_t)gg * NV * H + hb * HB;
        const uint32_t sb = (uint32_t)__cvta_generic_to_shared(&ysh[0]);
        const int nch = nact * (HB / 4);          // 16B chunks (16 per row)
        for (int s = t; s < nch; s += 128) {
            const int rw = s >> 4;
            const int q  = s & 15;
            cpa16(sb + (uint32_t)(rw * HB + q * 4) * 4,
                  ygb + (size_t)acts[rw] * H + q * 4);
        }
        asm volatile("cp.async.commit_group;");
        asm volatile("cp.async.wait_group 0;");
        __syncthreads();
    }

    float2 a2, acc;
    {
        const float2 c = *reinterpret_cast<const float2*>(
            g_C + (size_t)gg * NV * H + (size_t)row_i * H + hb * HB + 2 * col);
        a2.x = 0.5f * c.x;
        a2.y = 0.5f * c.y;
        acc.x = 0.0f;
        acc.y = 0.0f;
    }

    const float2* __restrict__ ys2 = reinterpret_cast<const float2*>(ysh);

    int jj = 0;
    for (; jj + 8 <= nact; jj += 8) {
        float2 yv[8];
#pragma unroll
        for (int u = 0; u < 8; u++) yv[u] = ys2[(jj + u) * HB2 + col];
#pragma unroll
        for (int u = 0; u < 8; u++) {
            acc.x += tanhx(fmaf(0.5f, yv[u].x, a2.x));
            acc.y += tanhx(fmaf(0.5f, yv[u].y, a2.y));
        }
    }
    for (; jj < nact; jj++) {
        const float2 y = ys2[jj * HB2 + col];
        acc.x += tanhx(fmaf(0.5f, y.x, a2.x));
        acc.y += tanhx(fmaf(0.5f, y.y, a2.y));
    }

    const float inv    = 1.0f / (float)nact;
    const float half_n = 0.5f * (float)nact;
    float2 v;
    if (rr < nact) {                     // straddling block's tail rows -> 0
        v.x = (0.5f * acc.x + half_n) * inv;
        v.y = (0.5f * acc.y + half_n) * inv;
    } else {
        v.x = 0.0f;
        v.y = 0.0f;
    }
    outp[0] = v;
}

// ---------------------------------------------------------------------------
// kernel_launch
// ---------------------------------------------------------------------------
extern "C" void kernel_launch(void* const* d_in, const int* in_sizes, int n_in,
                              void* d_out, int out_size)
{
    const float *z = nullptr, *mask = nullptr;
    const float *Wc = nullptr, *bc = nullptr, *Wy = nullptr, *by = nullptr;

    for (int i = 0; i < n_in; i++) {
        int s = in_sizes[i];
        const float* p = (const float*)d_in[i];
        if (s == M_ROWS * H)       z = p;
        else if (s == M_ROWS)      mask = p;
        else if (s == H * H)       { if (!Wc) Wc = p; else Wy = p; }
        else if (s == H)           { if (!bc) bc = p; else by = p; }
    }

    float* out = (float*)d_out;

    gemm_tc_kernel<<<dim3(H / 64, M_ROWS / 64, 2), 256>>>(z, Wc, bc, Wy, by);

    const size_t ysmem = (size_t)NV * HB * sizeof(float);   // 16 KB worst case
    attn_kernel<<<dim3(NV / RPB, G, H / HB), 128, ysmem>>>(mask, out);
}

// round 12
// speedup vs baseline: 1.0609x; 1.0135x over previous
#include <cuda_runtime.h>
#include <cuda_bf16.h>
#include <cstdint>

#define G  32
#define NV 64
#define H  256
#define M_ROWS (G * NV)

// Scratch (allocation-free rule: __device__ globals)
__device__ float g_C[M_ROWS * H];
__device__ float g_Y[M_ROWS * H];

// ---------------------------------------------------------------------------
// Stage A: TF32 tensor-core GEMM, no explicit CVT (HMMA.tf32 reads top 19 bits).
//   out[m][n] = sum_h z[m][h] * W[n][h] + b[n]
// Block tile 64(M) x 64(N), KC=32 double-buffered cp.async, 8 warps,
// warp tile 16(M) x 32(N). Grid (H/64, M/64, 2) = 256 blocks.
// ---------------------------------------------------------------------------
#define KC   32
#define LDK  36
#define NCH  (H / KC)   // 8 chunks

__device__ __forceinline__ void cpa16(uint32_t dst, const float* src) {
    asm volatile("cp.async.cg.shared.global [%0], [%1], 16;" :: "r"(dst), "l"(src));
}

__device__ __forceinline__ void mma_tf32(float c[4], const uint32_t a[4], const uint32_t b[2]) {
    asm volatile(
        "mma.sync.aligned.m16n8k8.row.col.f32.tf32.tf32.f32 "
        "{%0,%1,%2,%3}, {%4,%5,%6,%7}, {%8,%9}, {%0,%1,%2,%3};"
        : "+f"(c[0]), "+f"(c[1]), "+f"(c[2]), "+f"(c[3])
        : "r"(a[0]), "r"(a[1]), "r"(a[2]), "r"(a[3]), "r"(b[0]), "r"(b[1]));
}

__global__ void __launch_bounds__(256, 2) gemm_tc_kernel(
    const float* __restrict__ z,
    const float* __restrict__ Wc, const float* __restrict__ bc,
    const float* __restrict__ Wy, const float* __restrict__ by)
{
    const float* __restrict__ W    = blockIdx.z ? Wy : Wc;
    const float* __restrict__ bias = blockIdx.z ? by : bc;
    float* __restrict__ outp       = blockIdx.z ? g_Y : g_C;

    __shared__ float As[2][64 * LDK];
    __shared__ float Bs[2][64 * LDK];

    const int t    = threadIdx.x;
    const int warp = t >> 5;
    const int lane = t & 31;
    const int g    = lane >> 2;
    const int tg   = lane & 3;
    const int wm   = warp & 3;
    const int wn   = warp >> 2;
    const int m0   = blockIdx.y * 64;
    const int n0   = blockIdx.x * 64;

    const int r0s = t >> 3,         kg0 = t & 7;
    const int r1s = (t + 256) >> 3, kg1 = (t + 256) & 7;

    float acc[4][4];
#pragma unroll
    for (int nt = 0; nt < 4; nt++)
#pragma unroll
        for (int i = 0; i < 4; i++) acc[nt][i] = 0.0f;

    auto issue = [&](int c) {
        const int buf = c & 1;
        const int kc0 = c * KC;
        uint32_t asb = (uint32_t)__cvta_generic_to_shared(&As[buf][0]);
        uint32_t bsb = (uint32_t)__cvta_generic_to_shared(&Bs[buf][0]);
        cpa16(asb + (uint32_t)(r0s * LDK + kg0 * 4) * 4, z + (size_t)(m0 + r0s) * H + kc0 + kg0 * 4);
        cpa16(asb + (uint32_t)(r1s * LDK + kg1 * 4) * 4, z + (size_t)(m0 + r1s) * H + kc0 + kg1 * 4);
        cpa16(bsb + (uint32_t)(r0s * LDK + kg0 * 4) * 4, W + (size_t)(n0 + r0s) * H + kc0 + kg0 * 4);
        cpa16(bsb + (uint32_t)(r1s * LDK + kg1 * 4) * 4, W + (size_t)(n0 + r1s) * H + kc0 + kg1 * 4);
        asm volatile("cp.async.commit_group;");
    };

    issue(0);

    for (int c = 0; c < NCH; c++) {
        if (c + 1 < NCH) {
            issue(c + 1);
            asm volatile("cp.async.wait_group 1;");
        } else {
            asm volatile("cp.async.wait_group 0;");
        }
        __syncthreads();

        const uint32_t* as = reinterpret_cast<const uint32_t*>(&As[c & 1][0]);
        const uint32_t* bs = reinterpret_cast<const uint32_t*>(&Bs[c & 1][0]);

#pragma unroll
        for (int ks = 0; ks < KC / 8; ks++) {
            const int kk = ks * 8;
            uint32_t afr[4];
            {
                const uint32_t* ap = as + (wm * 16 + g) * LDK + kk + tg;
                afr[0] = ap[0];
                afr[1] = ap[8 * LDK];
                afr[2] = ap[4];
                afr[3] = ap[8 * LDK + 4];
            }
            uint32_t bfr[4][2];
#pragma unroll
            for (int nt = 0; nt < 4; nt++) {
                const uint32_t* bp = bs + (wn * 32 + nt * 8 + g) * LDK + kk + tg;
                bfr[nt][0] = bp[0];
                bfr[nt][1] = bp[4];
            }
#pragma unroll
            for (int nt = 0; nt < 4; nt++)
                mma_tf32(acc[nt], afr, bfr[nt]);
        }
        __syncthreads();
    }

#pragma unroll
    for (int nt = 0; nt < 4; nt++) {
        const int col = n0 + wn * 32 + nt * 8 + 2 * tg;
        const float b0 = __ldg(&bias[col]);
        const float b1 = __ldg(&bias[col + 1]);
        const int row = m0 + wm * 16 + g;
        float2 o0 = {acc[nt][0] + b0, acc[nt][1] + b1};
        float2 o1 = {acc[nt][2] + b0, acc[nt][3] + b1};
        *reinterpret_cast<float2*>(&outp[(size_t)row * H + col])       = o0;
        *reinterpret_cast<float2*>(&outp[(size_t)(row + 8) * H + col]) = o1;
    }
}

// ---------------------------------------------------------------------------
// Stage B: pairwise sigmoid sum.
// Block = 256 threads = 32 float2-cols x 8 rows (warp w owns row r0+w).
// Each block covers a QUARTER of H (HB=64 floats) -> dynamic smem 16 KB,
// 8 blocks/SM (2048-thread cap). Grid (NV/8, G, 4) = 1024 blocks ~ 1 wave.
// Per-block fixed costs (compaction + compacted cp.async fill + barrier)
// amortized over 8 rows; C-row load overlapped with the fill.
// Linear LDS.64 -> FFMA(imm 0.5) -> MUFU.TANH -> FADD, j unrolled x8.
// sigmoid(x)=0.5*tanh(0.5*x)+0.5 folded. Output row stride H floats.
// ---------------------------------------------------------------------------
#define RPB  8
#define HB   64          // h floats per block
#define HB2  (HB / 2)    // float2 cols per block = 32

__device__ __forceinline__ float tanhx(float x) {
    float th;
    asm("tanh.approx.f32 %0, %1;" : "=f"(th) : "f"(x));
    return th;
}

__global__ void __launch_bounds__(256) attn_kernel(
    const float* __restrict__ mask, float* __restrict__ out)
{
    extern __shared__ float ysh[];       // [NV rows][64 floats] compacted
    __shared__ int acts[NV];
    __shared__ int s_cnt[2];
    __shared__ int s_nact;

    const int gg  = blockIdx.y;
    const int r0  = blockIdx.x * RPB;
    const int hb  = blockIdx.z;          // h quarter
    const int t   = threadIdx.x;
    const int col = t & 31;              // float2 col within quarter
    const int r   = t >> 5;              // 0..7 row slot (== warp id)

    // ---- in-block compaction (threads 0..63; syncs unguarded) ----
    bool act = false;
    unsigned bal = 0;
    if (t < NV) {
        act = (mask[gg * NV + t] > 0.5f);
        bal = __ballot_sync(0xffffffffu, act);
        if ((t & 31) == 0) s_cnt[t >> 5] = __popc(bal);
    }
    __syncthreads();
    if (t < NV) {
        const int warp = t >> 5, lane = t & 31;
        const int a0 = s_cnt[0], a1 = s_cnt[1];
        const int nact = a0 + a1;
        const int pre  = __popc(bal & ((1u << lane) - 1u));
        const int preI = lane - pre;
        const int pos = act ? ((warp ? a0 : 0) + pre)
                            : (nact + (warp ? (32 - a0) : 0) + preI);
        acts[pos] = t;
        if (t == 0) s_nact = nact;
    }
    __syncthreads();

    const int nact  = s_nact;
    const int rr    = r0 + r;
    const int row_i = acts[rr];          // rr <= 63 always

    float2* __restrict__ outp = reinterpret_cast<float2*>(
        out + (size_t)gg * NV * H + (size_t)row_i * H + hb * HB) + col;

    if (r0 >= nact) {                    // fully inactive block
        outp[0] = make_float2(0.0f, 0.0f);
        return;
    }

    // ---- compacted fill (issue), then C-row load (overlaps), then wait ----
    {
        const float* __restrict__ ygb = g_Y + (size_t)gg * NV * H + hb * HB;
        const uint32_t sb = (uint32_t)__cvta_generic_to_shared(&ysh[0]);
        const int nch = nact * (HB / 4);          // 16B chunks (16 per row)
        for (int s = t; s < nch; s += 256) {
            const int rw = s >> 4;
            const int q  = s & 15;
            cpa16(sb + (uint32_t)(rw * HB + q * 4) * 4,
                  ygb + (size_t)acts[rw] * H + q * 4);
        }
        asm volatile("cp.async.commit_group;");
    }

    float2 a2, acc;
    {
        const float2 c = __ldg(reinterpret_cast<const float2*>(
            g_C + (size_t)gg * NV * H + (size_t)row_i * H + hb * HB) + col);
        a2.x = 0.5f * c.x;
        a2.y = 0.5f * c.y;
        acc.x = 0.0f;
        acc.y = 0.0f;
    }

    asm volatile("cp.async.wait_group 0;");
    __syncthreads();

    const float2* __restrict__ ys2 = reinterpret_cast<const float2*>(ysh);

    int jj = 0;
    for (; jj + 8 <= nact; jj += 8) {
        float2 yv[8];
#pragma unroll
        for (int u = 0; u < 8; u++) yv[u] = ys2[(jj + u) * HB2 + col];
#pragma unroll
        for (int u = 0; u < 8; u++) {
            acc.x += tanhx(fmaf(0.5f, yv[u].x, a2.x));
            acc.y += tanhx(fmaf(0.5f, yv[u].y, a2.y));
        }
    }
    for (; jj < nact; jj++) {
        const float2 y = ys2[jj * HB2 + col];
        acc.x += tanhx(fmaf(0.5f, y.x, a2.x));
        acc.y += tanhx(fmaf(0.5f, y.y, a2.y));
    }

    const float inv    = 1.0f / (float)nact;
    const float half_n = 0.5f * (float)nact;
    float2 v;
    if (rr < nact) {                     // straddling block's tail rows -> 0
        v.x = (0.5f * acc.x + half_n) * inv;
        v.y = (0.5f * acc.y + half_n) * inv;
    } else {
        v.x = 0.0f;
        v.y = 0.0f;
    }
    outp[0] = v;
}

// ---------------------------------------------------------------------------
// kernel_launch
// ---------------------------------------------------------------------------
extern "C" void kernel_launch(void* const* d_in, const int* in_sizes, int n_in,
                              void* d_out, int out_size)
{
    const float *z = nullptr, *mask = nullptr;
    const float *Wc = nullptr, *bc = nullptr, *Wy = nullptr, *by = nullptr;

    for (int i = 0; i < n_in; i++) {
        int s = in_sizes[i];
        const float* p = (const float*)d_in[i];
        if (s == M_ROWS * H)       z = p;
        else if (s == M_ROWS)      mask = p;
        else if (s == H * H)       { if (!Wc) Wc = p; else Wy = p; }
        else if (s == H)           { if (!bc) bc = p; else by = p; }
    }

    float* out = (float*)d_out;

    gemm_tc_kernel<<<dim3(H / 64, M_ROWS / 64, 2), 256>>>(z, Wc, bc, Wy, by);

    const size_t ysmem = (size_t)NV * HB * sizeof(float);   // 16 KB worst case
    attn_kernel<<<dim3(NV / RPB, G, H / HB), 256, ysmem>>>(mask, out);
}